// round 1
// baseline (speedup 1.0000x reference)
#include <cuda_runtime.h>
#include <cuda_bf16.h>
#include <stdint.h>

#define B 32
#define H 512
#define W 512
#define HW (H*W)            // 262144
#define WW 16               // words per row (512/32)
#define SSTRIDE 18          // smem row stride in words (bank-conflict-free for strip layout)

__device__ unsigned char g_gray[B*HW];       // 8.4 MB
__device__ unsigned      g_weak[B*H*WW];     // 1 MB
__device__ unsigned      g_strong[B*H*WW];   // 1 MB

// ---------------- Kernel 1: RGB -> gray (u8) ----------------
__device__ __forceinline__ float u8f(float v) {
    // floor(clip((v+1)*0.5*256, 0, 255)); (v+1)*128 is bit-identical (exact scalings)
    float t = __fmul_rn(__fadd_rn(v, 1.0f), 128.0f);
    t = fminf(fmaxf(t, 0.0f), 255.0f);
    return floorf(t);
}

__device__ __forceinline__ unsigned char grayf(float r, float g, float b) {
    float t = __fadd_rn(__fadd_rn(__fmul_rn(0.299f, u8f(r)),
                                  __fmul_rn(0.587f, u8f(g))),
                        __fmul_rn(0.114f, u8f(b)));
    return (unsigned char)rintf(t);   // round half to even, matches jnp.round
}

__global__ void k_gray(const float* __restrict__ x) {
    int i = blockIdx.x * blockDim.x + threadIdx.x;   // pixel4 index
    if (i >= B * (HW/4)) return;
    int b  = i >> 16;          // / 65536
    int p4 = i & 65535;
    const float4* base = (const float4*)(x + (size_t)b * 3 * HW);
    float4 r  = base[p4];
    float4 g  = base[65536 + p4];
    float4 bl = base[131072 + p4];
    uchar4 o;
    o.x = grayf(r.x, g.x, bl.x);
    o.y = grayf(r.y, g.y, bl.y);
    o.z = grayf(r.z, g.z, bl.z);
    o.w = grayf(r.w, g.w, bl.w);
    ((uchar4*)g_gray)[i] = o;
}

// ------------- Kernel 2: Sobel + NMS + thresholds -> bitmasks -------------
// Tile 128x8 per block, block (128,8). Gray halo 2, mag halo 1.
__global__ void k_sobel(void) {
    __shared__ int G[12][132];   // gray tile with halo 2
    __shared__ int M[10][132];   // mag tile with halo 1 (valid cols 0..129)

    int b = blockIdx.z;
    int tileX = blockIdx.x * 128, tileY = blockIdx.y * 8;
    int tx = threadIdx.x, ty = threadIdx.y;
    int tid = ty * 128 + tx;
    const unsigned char* gb = g_gray + (size_t)b * HW;

    for (int i = tid; i < 12 * 132; i += 1024) {
        int r = i / 132, c = i - r * 132;
        int gy = min(max(tileY - 2 + r, 0), H - 1);   // replicate border
        int gx = min(max(tileX - 2 + c, 0), W - 1);
        G[r][c] = gb[gy * W + gx];
    }
    __syncthreads();

    for (int i = tid; i < 10 * 130; i += 1024) {
        int r = i / 130, c = i - r * 130;
        int py = tileY - 1 + r, px = tileX - 1 + c;
        int m = 0;
        if (py >= 0 && py < H && px >= 0 && px < W) {   // mag zero-padded outside image
            int r0 = r + 1, c0 = c + 1;
            int gxv = (G[r0-1][c0+1] + 2*G[r0][c0+1] + G[r0+1][c0+1])
                    - (G[r0-1][c0-1] + 2*G[r0][c0-1] + G[r0+1][c0-1]);
            int gyv = (G[r0+1][c0-1] + 2*G[r0+1][c0] + G[r0+1][c0+1])
                    - (G[r0-1][c0-1] + 2*G[r0-1][c0] + G[r0-1][c0+1]);
            m = abs(gxv) + abs(gyv);
        }
        M[r][c] = m;
    }
    __syncthreads();

    int py = tileY + ty, px = tileX + tx;
    int r0 = ty + 2, c0 = tx + 2;
    int gxv = (G[r0-1][c0+1] + 2*G[r0][c0+1] + G[r0+1][c0+1])
            - (G[r0-1][c0-1] + 2*G[r0][c0-1] + G[r0+1][c0-1]);
    int gyv = (G[r0+1][c0-1] + 2*G[r0+1][c0] + G[r0+1][c0+1])
            - (G[r0-1][c0-1] + 2*G[r0-1][c0] + G[r0-1][c0+1]);
    int mr = ty + 1, mc = tx + 1;
    int m  = M[mr][mc];

    int ax = abs(gxv), ay = abs(gyv);
    double dax = (double)ax, day = (double)ay;
    int q1, q2;
    if (day < 0.41421356237309503 * dax) {            // b0: ~horizontal gradient
        q1 = M[mr][mc + 1]; q2 = M[mr][mc - 1];
    } else if (day > 2.414213562373095 * dax) {       // b2
        q1 = M[mr + 1][mc]; q2 = M[mr - 1][mc];
    } else if ((gxv > 0) == (gyv > 0)) {              // b1
        q1 = M[mr + 1][mc + 1]; q2 = M[mr - 1][mc - 1];
    } else {                                          // b3
        q1 = M[mr - 1][mc + 1]; q2 = M[mr + 1][mc - 1];
    }
    bool keep   = (m >= q1) && (m >= q2);
    bool weak   = keep && (m > 40);     // nms > 40.0 (integer mag)
    bool strong = keep && (m > 85);     // nms > 85.0

    unsigned wmask = __ballot_sync(0xffffffffu, weak);
    unsigned smask = __ballot_sync(0xffffffffu, strong);
    if ((tx & 31) == 0) {
        int wi = b * (H * WW) + py * WW + (px >> 5);
        g_weak[wi]   = wmask;
        g_strong[wi] = smask;
    }
}

// ------------- Kernel 3: in-SMEM hysteresis (Jacobi, early exit) -------------
// One block per batch image. Full 512x512 bitmask in shared memory.
// Thread t: column word xw = t&15, rows y0..y0+7 with y0 = (t>>4)*8.
__global__ void __launch_bounds__(1024, 1) k_hyst(float* __restrict__ out) {
    __shared__ unsigned S[H * SSTRIDE];
    __shared__ int chg;
    int tid = threadIdx.x;
    int b = blockIdx.x;
    int xw = tid & 15;
    int y0 = (tid >> 4) * 8;

    const unsigned* wb = g_weak   + b * (H * WW);
    const unsigned* sb = g_strong + b * (H * WW);
    unsigned wkr[8];
#pragma unroll
    for (int i = 0; i < 8; i++) {
        int row = y0 + i;
        wkr[i] = wb[row * WW + xw];
        S[row * SSTRIDE + xw] = sb[row * WW + xw];
    }
    if (tid == 0) chg = 0;
    __syncthreads();

    for (int it = 0; it < 100; ++it) {
        unsigned h[10], oldv[8];
#pragma unroll
        for (int k = 0; k < 10; k++) {
            int row = y0 - 1 + k;
            if (row < 0 || row > H - 1) { h[k] = 0u; continue; }
            unsigned c = S[row * SSTRIDE + xw];
            unsigned l = (xw > 0)  ? S[row * SSTRIDE + xw - 1] : 0u;
            unsigned r = (xw < 15) ? S[row * SSTRIDE + xw + 1] : 0u;
            if (k >= 1 && k <= 8) oldv[k - 1] = c;
            h[k] = c | (c << 1) | (c >> 1) | (l >> 31) | (r << 31);
        }
        unsigned nw[8];
        bool diff = false;
#pragma unroll
        for (int i = 0; i < 8; i++) {
            nw[i] = wkr[i] & (h[i] | h[i + 1] | h[i + 2]);
            diff |= (nw[i] != oldv[i]);
        }
        __syncthreads();                  // all reads of S done
#pragma unroll
        for (int i = 0; i < 8; i++) S[(y0 + i) * SSTRIDE + xw] = nw[i];
        unsigned dmask = __ballot_sync(0xffffffffu, diff);
        if ((tid & 31) == 0 && dmask) atomicOr(&chg, 1);
        __syncthreads();                  // writes + flag visible
        int c2 = chg;
        __syncthreads();                  // everyone read flag
        if (tid == 0) chg = 0;
        if (!c2) break;                   // converged -> fixed point == 100-iter result
        __syncthreads();                  // reset visible before next flag set
    }
    __syncthreads();

    float* ob = out + (size_t)b * HW;
    for (int p = tid; p < HW; p += 1024) {
        int y = p >> 9, x = p & 511;
        unsigned w = S[y * SSTRIDE + (x >> 5)];
        ob[p] = ((w >> (x & 31)) & 1u) ? 255.0f : 0.0f;
    }
}

extern "C" void kernel_launch(void* const* d_in, const int* in_sizes, int n_in,
                              void* d_out, int out_size) {
    const float* x = (const float*)d_in[0];
    float* out = (float*)d_out;

    k_gray<<<(B * (HW/4) + 255) / 256, 256>>>(x);
    k_sobel<<<dim3(W/128, H/8, B), dim3(128, 8)>>>();
    k_hyst<<<B, 1024>>>(out);
}